// round 15
// baseline (speedup 1.0000x reference)
#include <cuda_runtime.h>
#include <cuda_fp16.h>
#include <cstdint>
#include <math.h>

// Problem constants
#define TT   8192
#define DD   1024
#define EE   8
#define FFD  3584

// GEMM tiling (fp16 mma.sync m16n8k16)
#define BM   128
#define BN   128
#define BK   64     // halves per stage-K: 64 x 2B = 128B per row
#define PADK 72     // 72-half row stride: 144B, conflict-free frag loads
#define NSTAGE 3

#define MPMAX  (2*TT + EE*BM)   // 17408 max padded slot rows
#define MTILES (MPMAX/BM)       // 136

// ---------------- scratch (device globals; no allocation allowed) ----------------
__device__ __half g_xh [(size_t)MPMAX * DD];    // gathered fp16 x
__device__ __half g_h  [(size_t)MPMAX * FFD];   // silu(G)*U, fp16
__device__ __half g_w1h[(size_t)EE * FFD * DD]; // fp16 weights
__device__ __half g_w3h[(size_t)EE * FFD * DD];
__device__ __half g_w2h[(size_t)EE * DD * FFD];
__device__ int    g_perm[MPMAX];                // slot -> token (-1 = pad)
__device__ float  g_pw  [MPMAX];                // slot -> routing weight
__device__ int    g_ridx[TT * 2];
__device__ float  g_rw  [TT * 2];
__device__ int    g_cnt [EE];
__device__ int    g_poff[EE + 1];

// ---------------- helpers ----------------
__device__ __forceinline__ void cp16(uint32_t saddr, const void* gptr) {
    asm volatile("cp.async.cg.shared.global [%0], [%1], 16;" :: "r"(saddr), "l"(gptr));
}
__device__ __forceinline__ void cp_commit() {
    asm volatile("cp.async.commit_group;" ::: "memory");
}
__device__ __forceinline__ void mma16(float (&d)[4], const uint32_t (&a)[4], const uint32_t (&b)[2]) {
    asm volatile(
        "mma.sync.aligned.m16n8k16.row.col.f32.f16.f16.f32 "
        "{%0,%1,%2,%3},{%4,%5,%6,%7},{%8,%9},{%0,%1,%2,%3};"
        : "+f"(d[0]), "+f"(d[1]), "+f"(d[2]), "+f"(d[3])
        : "r"(a[0]), "r"(a[1]), "r"(a[2]), "r"(a[3]), "r"(b[0]), "r"(b[1]));
}
__device__ __forceinline__ float silu_mul(float gv, float uv) {
    return (gv / (1.0f + __expf(-gv))) * uv;
}
__device__ __forceinline__ uint32_t pack_h2(float a, float b) {
    __half2 h = __floats2half2_rn(a, b);
    return *reinterpret_cast<uint32_t*>(&h);
}

// ---------------- routing: softmax-top2 == softmax over the top-2 logits ----------------
__global__ void k_route(const float* __restrict__ logits) {
    int t = blockIdx.x * blockDim.x + threadIdx.x;
    if (t >= TT) return;
    float v[EE];
#pragma unroll
    for (int e = 0; e < EE; e++) v[e] = logits[t * EE + e];
    int i0 = 0; float b0 = v[0];
#pragma unroll
    for (int e = 1; e < EE; e++) if (v[e] > b0) { b0 = v[e]; i0 = e; }
    int i1 = -1; float b1 = -INFINITY;
#pragma unroll
    for (int e = 0; e < EE; e++) if (e != i0 && v[e] > b1) { b1 = v[e]; i1 = e; }
    float w0 = 1.0f / (1.0f + __expf(b1 - b0));
    g_ridx[2 * t] = i0;  g_ridx[2 * t + 1] = i1;
    g_rw  [2 * t] = w0;  g_rw  [2 * t + 1] = 1.0f - w0;
}

// counts + padded offsets in one single-block kernel
__global__ void k_count_off() {
    int tid = threadIdx.x;
    __shared__ int cnt[EE];
    if (tid < EE) cnt[tid] = 0;
    __syncthreads();
    int local[EE];
#pragma unroll
    for (int e = 0; e < EE; e++) local[e] = 0;
    for (int i = tid; i < 2 * TT; i += 256) local[g_ridx[i]]++;
#pragma unroll
    for (int e = 0; e < EE; e++) if (local[e]) atomicAdd(&cnt[e], local[e]);
    __syncthreads();
    if (tid == 0) {
        int acc = 0;
        g_poff[0] = 0;
        for (int e = 0; e < EE; e++) {
            g_cnt[e] = cnt[e];
            acc += ((cnt[e] + BM - 1) / BM) * BM;
            g_poff[e + 1] = acc;
        }
    }
}

// stable (token-order) scatter via ballot scan; deterministic
// also records per-slot routing weight for the fused combine in GEMM2's epilogue
__global__ void k_scatter() {
    int e = blockIdx.x, tid = threadIdx.x;
    int warp = tid >> 5, lane = tid & 31;
    __shared__ int wsum[8];
    __shared__ int base;
    if (tid == 0) base = 0;
    __syncthreads();
    int off = g_poff[e];
    for (int b = 0; b < TT; b += 256) {
        int t = b + tid;
        int which = -1;
        if (g_ridx[2 * t] == e) which = 0;
        else if (g_ridx[2 * t + 1] == e) which = 1;
        unsigned mask = __ballot_sync(0xffffffffu, which >= 0);
        int lp = __popc(mask & ((1u << lane) - 1));
        if (lane == 0) wsum[warp] = __popc(mask);
        __syncthreads();
        if (which >= 0) {
            int woff = 0;
#pragma unroll
            for (int w = 0; w < 8; w++) if (w < warp) woff += wsum[w];
            int pos = base + woff + lp;
            g_perm[off + pos] = t;
            g_pw  [off + pos] = g_rw[2 * t + which];
        }
        __syncthreads();
        if (tid == 0) {
            int tot = 0;
#pragma unroll
            for (int w = 0; w < 8; w++) tot += wsum[w];
            base += tot;
        }
        __syncthreads();
    }
    int cnt = g_cnt[e];
    for (int p = off + cnt + tid; p < g_poff[e + 1]; p += 256) {
        g_perm[p] = -1;
        g_pw  [p] = 0.f;
    }
}

// gather x rows into slot order, RN-converted to fp16
__global__ void k_gather(const float* __restrict__ x) {
    int row = blockIdx.x;
    if (row >= g_poff[EE]) return;
    int t = g_perm[row];
    int i = threadIdx.x;                     // 256 threads x 4 elems = 1024
    float4 v = make_float4(0.f, 0.f, 0.f, 0.f);
    if (t >= 0) v = reinterpret_cast<const float4*>(x + (size_t)t * DD)[i];
    uint2 p;
    p.x = pack_h2(v.x, v.y);
    p.y = pack_h2(v.z, v.w);
    reinterpret_cast<uint2*>(g_xh + (size_t)row * DD)[i] = p;
}

// zero the output (poisoned 0xAA by the harness); GEMM2 accumulates into it
__global__ void k_zero(float* __restrict__ out) {
    int i = blockIdx.x * blockDim.x + threadIdx.x;
    reinterpret_cast<float4*>(out)[i] = make_float4(0.f, 0.f, 0.f, 0.f);
}

// convert all three weight tensors fp32 -> fp16 (RN) in one launch
#define WELEM4 (EE * FFD * DD / 4)   // float4 groups per tensor
__global__ void k_halfw(const float* __restrict__ w1, const float* __restrict__ w3,
                        const float* __restrict__ w2,
                        __half* __restrict__ d1, __half* __restrict__ d3,
                        __half* __restrict__ d2) {
    int i = blockIdx.x * blockDim.x + threadIdx.x;
    const float* src; __half* dst; int k = i;
    if (i < WELEM4)               { src = w1; dst = d1; }
    else if (i < 2 * WELEM4)      { src = w3; dst = d3; k = i - WELEM4; }
    else                          { src = w2; dst = d2; k = i - 2 * WELEM4; }
    float4 v = reinterpret_cast<const float4*>(src)[k];
    uint2 p;
    p.x = pack_h2(v.x, v.y);
    p.y = pack_h2(v.z, v.w);
    reinterpret_cast<uint2*>(dst)[k] = p;
}

// ---------------- grouped GEMM (mma.sync m16n8k16 fp16, fp32 accumulate) ----------------
// FUSED=true : 512 threads, 16 warps as 4x4 grid of 32x32 warp tiles.
//              A=g_xh [M,1024], B1=w1h, B3=w3h; C=g_h (fp16 silu(G)*U)
// FUSED=false: 256 threads, 8 warps as 2x4 grid of 64x32 warp tiles (2 CTAs/SM).
//              A=g_h  [M,3584], B1=w2h; epilogue: out[token] += w_slot * acc
//              (fp32 atomicAdd; exactly 2 commutative contributions per element
//               -> bitwise deterministic; accumulators never rounded to fp16)
// 3-stage cp.async pipeline, ONE __syncthreads per kt. Per-element K-summation
// order identical across both layouts.
template<int KD, bool FUSED, int MINB>
__global__ void __launch_bounds__(FUSED ? 512 : 256, MINB)
k_gemm(const __half* __restrict__ B1g, const __half* __restrict__ B3g,
       float* __restrict__ outp) {
    constexpr int NTH   = FUSED ? 512 : 256;
    constexpr int MI    = FUSED ? 2 : 4;           // 16-row groups per warp tile
    constexpr int NB    = FUSED ? 2 : 1;
    constexpr int STAGE = (BM + NB * BN) * PADK;   // halves per stage
    constexpr int NK    = KD / BK;
    constexpr int NROWS = FUSED ? FFD : DD;

    extern __shared__ __half smem[];

    int m0 = blockIdx.y * BM;
    if (m0 >= g_poff[EE]) return;
    int e = 0;
#pragma unroll
    for (int i = 1; i < EE; i++) if (m0 >= g_poff[i]) e = i;

    int n0 = blockIdx.x * BN;
    const __half* Ap  = (FUSED ? g_xh : g_h) + (size_t)m0 * KD;
    const __half* B1p = B1g + ((size_t)e * NROWS + n0) * KD;
    const __half* B3p = FUSED ? (B3g + ((size_t)e * FFD + n0) * KD) : nullptr;

    uint32_t sbase = (uint32_t)__cvta_generic_to_shared(smem);
    int tid = threadIdx.x;

    auto load_stage = [&](int kt, int buf) {
        uint32_t sb = sbase + (uint32_t)buf * STAGE * 2;
        int k0 = kt * BK;
        for (int ch = tid; ch < BM * 8; ch += NTH) {       // A: 128 rows x 8 chunks
            int row = ch >> 3, kc = (ch & 7) * 8;
            cp16(sb + (uint32_t)(row * PADK + kc) * 2, Ap + (size_t)row * KD + k0 + kc);
        }
        for (int ch = tid; ch < BN * 8; ch += NTH) {       // B1: 128 rows x 8 chunks
            int row = ch >> 3, kc = (ch & 7) * 8;
            cp16(sb + (uint32_t)((BM + row) * PADK + kc) * 2,
                 B1p + (size_t)row * KD + k0 + kc);
        }
        if (FUSED) {
            for (int ch = tid; ch < BN * 8; ch += NTH) {   // B3
                int row = ch >> 3, kc = (ch & 7) * 8;
                cp16(sb + (uint32_t)((BM + BN + row) * PADK + kc) * 2,
                     B3p + (size_t)row * KD + k0 + kc);
            }
        }
        cp_commit();
    };

    int warp = tid >> 5, lane = tid & 31;
    int wm = warp >> 2, wn = warp & 3;   // FUSED: 4x4 warps (32x32); else 2x4 (64x32)
    int g = lane >> 2, tg = lane & 3;

    float accG[MI][4][4];
    float accU[MI][4][4];
#pragma unroll
    for (int i = 0; i < MI; i++)
#pragma unroll
        for (int j = 0; j < 4; j++)
#pragma unroll
            for (int l = 0; l < 4; l++) {
                accG[i][j][l] = 0.f;
                if (FUSED) accU[i][j][l] = 0.f;
            }

    load_stage(0, 0);
    load_stage(1, 1);

    int buf = 0;
    for (int kt = 0; kt < NK; ++kt) {
        if (kt < NK - 1) { asm volatile("cp.async.wait_group 1;" ::: "memory"); }
        else             { asm volatile("cp.async.wait_group 0;" ::: "memory"); }
        __syncthreads();   // single barrier per kt; also protects buffer (kt+2)%3 reload

        if (kt + 2 < NK) load_stage(kt + 2, (buf + 2) % NSTAGE);

        const __half* s   = smem + (size_t)buf * STAGE;
        const __half* sA  = s;
        const __half* sB1 = s + BM * PADK;
        const __half* sB3 = sB1 + BN * PADK;

#pragma unroll
        for (int ks = 0; ks < BK / 16; ks++) {       // k16 per mma
            int kk = ks * 16;
            uint32_t a[MI][4];
#pragma unroll
            for (int i = 0; i < MI; i++) {
                int r = wm * (MI * 16) + i * 16 + g;
                a[i][0] = *reinterpret_cast<const uint32_t*>(sA + r * PADK + kk + 2 * tg);
                a[i][1] = *reinterpret_cast<const uint32_t*>(sA + (r + 8) * PADK + kk + 2 * tg);
                a[i][2] = *reinterpret_cast<const uint32_t*>(sA + r * PADK + kk + 8 + 2 * tg);
                a[i][3] = *reinterpret_cast<const uint32_t*>(sA + (r + 8) * PADK + kk + 8 + 2 * tg);
            }
#pragma unroll
            for (int j = 0; j < 4; j++) {
                int n = wn * 32 + j * 8 + g;
                uint32_t b1[2];
                b1[0] = *reinterpret_cast<const uint32_t*>(sB1 + n * PADK + kk + 2 * tg);
                b1[1] = *reinterpret_cast<const uint32_t*>(sB1 + n * PADK + kk + 8 + 2 * tg);
#pragma unroll
                for (int i = 0; i < MI; i++) mma16(accG[i][j], a[i], b1);
                if (FUSED) {
                    uint32_t b3[2];
                    b3[0] = *reinterpret_cast<const uint32_t*>(sB3 + n * PADK + kk + 2 * tg);
                    b3[1] = *reinterpret_cast<const uint32_t*>(sB3 + n * PADK + kk + 8 + 2 * tg);
#pragma unroll
                    for (int i = 0; i < MI; i++) mma16(accU[i][j], a[i], b3);
                }
            }
        }
        buf = (buf + 1) % NSTAGE;
    }

    // epilogue
#pragma unroll
    for (int i = 0; i < MI; i++) {
        int r = m0 + wm * (MI * 16) + i * 16 + g;
        if (FUSED) {
#pragma unroll
            for (int j = 0; j < 4; j++) {
                int c = n0 + wn * 32 + j * 8 + 2 * tg;
                float h0 = silu_mul(accG[i][j][0], accU[i][j][0]);
                float h1 = silu_mul(accG[i][j][1], accU[i][j][1]);
                float h2 = silu_mul(accG[i][j][2], accU[i][j][2]);
                float h3 = silu_mul(accG[i][j][3], accU[i][j][3]);
                *reinterpret_cast<uint32_t*>(g_h + (size_t)r * FFD + c)       = pack_h2(h0, h1);
                *reinterpret_cast<uint32_t*>(g_h + (size_t)(r + 8) * FFD + c) = pack_h2(h2, h3);
            }
        } else {
            // fused combine: out[token] += w_slot * acc (2 commutative fp32 adds/elem)
            int   t0 = g_perm[r],     t1 = g_perm[r + 8];
            float q0 = g_pw[r],       q1 = g_pw[r + 8];
            float* o0 = outp + (size_t)(t0 < 0 ? 0 : t0) * DD;
            float* o1 = outp + (size_t)(t1 < 0 ? 0 : t1) * DD;
#pragma unroll
            for (int j = 0; j < 4; j++) {
                int c = n0 + wn * 32 + j * 8 + 2 * tg;
                if (t0 >= 0) {
                    atomicAdd(o0 + c,     q0 * accG[i][j][0]);
                    atomicAdd(o0 + c + 1, q0 * accG[i][j][1]);
                }
                if (t1 >= 0) {
                    atomicAdd(o1 + c,     q1 * accG[i][j][2]);
                    atomicAdd(o1 + c + 1, q1 * accG[i][j][3]);
                }
            }
        }
    }
}

// ---------------- launch ----------------
extern "C" void kernel_launch(void* const* d_in, const int* in_sizes, int n_in,
                              void* d_out, int out_size) {
    const float* x      = (const float*)d_in[0];
    const float* w1     = (const float*)d_in[1];
    const float* w3     = (const float*)d_in[2];
    const float* w2     = (const float*)d_in[3];
    const float* logits = (const float*)d_in[4];
    float* out = (float*)d_out;

    constexpr int SMEM1 = NSTAGE * (BM + 2 * BN) * PADK * 2;  // 165888 B (1 CTA/SM)
    constexpr int SMEM2 = NSTAGE * (BM + 1 * BN) * PADK * 2;  // 110592 B (2 CTAs/SM)
    cudaFuncSetAttribute((const void*)k_gemm<DD,  true,  1>,
                         cudaFuncAttributeMaxDynamicSharedMemorySize, SMEM1);
    cudaFuncSetAttribute((const void*)k_gemm<FFD, false, 2>,
                         cudaFuncAttributeMaxDynamicSharedMemorySize, SMEM2);

    __half* w1h; cudaGetSymbolAddress((void**)&w1h, g_w1h);
    __half* w3h; cudaGetSymbolAddress((void**)&w3h, g_w3h);
    __half* w2h; cudaGetSymbolAddress((void**)&w2h, g_w2h);

    k_route    <<<TT / 256, 256>>>(logits);
    k_count_off<<<1, 256>>>();
    k_scatter  <<<EE, 256>>>();
    k_gather   <<<MPMAX, 256>>>(x);
    k_zero     <<<TT * DD / 4 / 256, 256>>>(out);
    k_halfw    <<<3 * WELEM4 / 256, 256>>>(w1, w3, w2, w1h, w3h, w2h);

    k_gemm<DD,  true,  1><<<dim3(FFD / BN, MTILES), 512, SMEM1>>>(w1h, w3h, nullptr);
    k_gemm<FFD, false, 2><<<dim3(DD  / BN, MTILES), 256, SMEM2>>>(w2h, nullptr, out);
}

// round 16
// speedup vs baseline: 1.0173x; 1.0173x over previous
#include <cuda_runtime.h>
#include <cuda_fp16.h>
#include <cstdint>
#include <math.h>

// Problem constants
#define TT   8192
#define DD   1024
#define EE   8
#define FFD  3584

// GEMM tiling (fp16 mma.sync m16n8k16)
#define BM   128
#define BN   128
#define BK   64     // halves per stage-K: 64 x 2B = 128B per row
#define PADK 72     // 72-half row stride: 144B, conflict-free frag loads
#define NSTAGE 3

#define MPMAX  (2*TT + EE*BM)   // 17408 max padded slot rows
#define MTILES (MPMAX/BM)       // 136

// ---------------- scratch (device globals; no allocation allowed) ----------------
__device__ __half g_xh [(size_t)MPMAX * DD];    // gathered fp16 x
__device__ __half g_h  [(size_t)MPMAX * FFD];   // silu(G)*U, fp16
__device__ __half g_yh [(size_t)MPMAX * DD];    // per-slot expert output (fp16)
__device__ __half g_w1h[(size_t)EE * FFD * DD]; // fp16 weights
__device__ __half g_w3h[(size_t)EE * FFD * DD];
__device__ __half g_w2h[(size_t)EE * DD * FFD];
__device__ int    g_perm[MPMAX];
__device__ int    g_ridx[TT * 2];
__device__ float  g_rw  [TT * 2];
__device__ int    g_slot[TT * 2];
__device__ int    g_poff[EE + 1];

// ---------------- helpers ----------------
__device__ __forceinline__ void cp16(uint32_t saddr, const void* gptr) {
    asm volatile("cp.async.cg.shared.global [%0], [%1], 16;" :: "r"(saddr), "l"(gptr));
}
__device__ __forceinline__ void cp_commit() {
    asm volatile("cp.async.commit_group;" ::: "memory");
}
__device__ __forceinline__ void mma16(float (&d)[4], const uint32_t (&a)[4], const uint32_t (&b)[2]) {
    asm volatile(
        "mma.sync.aligned.m16n8k16.row.col.f32.f16.f16.f32 "
        "{%0,%1,%2,%3},{%4,%5,%6,%7},{%8,%9},{%0,%1,%2,%3};"
        : "+f"(d[0]), "+f"(d[1]), "+f"(d[2]), "+f"(d[3])
        : "r"(a[0]), "r"(a[1]), "r"(a[2]), "r"(a[3]), "r"(b[0]), "r"(b[1]));
}
__device__ __forceinline__ float silu_mul(float gv, float uv) {
    return (gv / (1.0f + __expf(-gv))) * uv;
}
__device__ __forceinline__ uint32_t pack_h2(float a, float b) {
    __half2 h = __floats2half2_rn(a, b);
    return *reinterpret_cast<uint32_t*>(&h);
}

// ---------------- routing: softmax-top2 == softmax over the top-2 logits ----------------
__global__ void k_route(const float* __restrict__ logits) {
    int t = blockIdx.x * blockDim.x + threadIdx.x;
    if (t >= TT) return;
    float v[EE];
#pragma unroll
    for (int e = 0; e < EE; e++) v[e] = logits[t * EE + e];
    int i0 = 0; float b0 = v[0];
#pragma unroll
    for (int e = 1; e < EE; e++) if (v[e] > b0) { b0 = v[e]; i0 = e; }
    int i1 = -1; float b1 = -INFINITY;
#pragma unroll
    for (int e = 0; e < EE; e++) if (e != i0 && v[e] > b1) { b1 = v[e]; i1 = e; }
    float w0 = 1.0f / (1.0f + __expf(b1 - b0));
    g_ridx[2 * t] = i0;  g_ridx[2 * t + 1] = i1;
    g_rw  [2 * t] = w0;  g_rw  [2 * t + 1] = 1.0f - w0;
}

// stable (token-order) scatter via ballot scan; deterministic.
// Counting + padded-offset computation folded in: each block scans g_ridx once
// (a pass it effectively pays anyway), derives all experts' padded offsets
// locally, and block 0 publishes g_poff for downstream kernels.
__global__ void k_scatter() {
    int e = blockIdx.x, tid = threadIdx.x;
    int warp = tid >> 5, lane = tid & 31;
    __shared__ int scnt[EE];
    __shared__ int spoff[EE + 1];
    __shared__ int wsum[8];
    __shared__ int base;
    if (tid < EE) scnt[tid] = 0;
    if (tid == 0) base = 0;
    __syncthreads();

    // phase 1: count all experts (register histogram -> shared atomics)
    {
        int local[EE];
#pragma unroll
        for (int k = 0; k < EE; k++) local[k] = 0;
        for (int i = tid; i < 2 * TT; i += 256) local[g_ridx[i]]++;
#pragma unroll
        for (int k = 0; k < EE; k++) if (local[k]) atomicAdd(&scnt[k], local[k]);
    }
    __syncthreads();
    if (tid == 0) {
        int acc = 0;
        spoff[0] = 0;
        for (int k = 0; k < EE; k++) {
            acc += ((scnt[k] + BM - 1) / BM) * BM;
            spoff[k + 1] = acc;
        }
        if (e == 0) {               // publish for gather / GEMMs (all blocks agree)
#pragma unroll
            for (int k = 0; k <= EE; k++) g_poff[k] = spoff[k];
        }
    }
    __syncthreads();
    int off = spoff[e];

    // phase 2: stable scatter for this expert
    for (int b = 0; b < TT; b += 256) {
        int t = b + tid;
        int which = -1;
        if (g_ridx[2 * t] == e) which = 0;
        else if (g_ridx[2 * t + 1] == e) which = 1;
        unsigned mask = __ballot_sync(0xffffffffu, which >= 0);
        int lp = __popc(mask & ((1u << lane) - 1));
        if (lane == 0) wsum[warp] = __popc(mask);
        __syncthreads();
        if (which >= 0) {
            int woff = 0;
#pragma unroll
            for (int w = 0; w < 8; w++) if (w < warp) woff += wsum[w];
            int pos = base + woff + lp;
            g_perm[off + pos] = t;
            g_slot[2 * t + which] = off + pos;
        }
        __syncthreads();
        if (tid == 0) {
            int tot = 0;
#pragma unroll
            for (int w = 0; w < 8; w++) tot += wsum[w];
            base += tot;
        }
        __syncthreads();
    }
    int cnt = scnt[e];
    for (int p = off + cnt + tid; p < spoff[e + 1]; p += 256) g_perm[p] = -1;
}

// gather x rows into slot order, RN-converted to fp16
__global__ void k_gather(const float* __restrict__ x) {
    int row = blockIdx.x;
    if (row >= g_poff[EE]) return;
    int t = g_perm[row];
    int i = threadIdx.x;                     // 256 threads x 4 elems = 1024
    float4 v = make_float4(0.f, 0.f, 0.f, 0.f);
    if (t >= 0) v = reinterpret_cast<const float4*>(x + (size_t)t * DD)[i];
    uint2 p;
    p.x = pack_h2(v.x, v.y);
    p.y = pack_h2(v.z, v.w);
    reinterpret_cast<uint2*>(g_xh + (size_t)row * DD)[i] = p;
}

// convert all three weight tensors fp32 -> fp16 (RN) in one launch
#define WELEM4 (EE * FFD * DD / 4)   // float4 groups per tensor
__global__ void k_halfw(const float* __restrict__ w1, const float* __restrict__ w3,
                        const float* __restrict__ w2,
                        __half* __restrict__ d1, __half* __restrict__ d3,
                        __half* __restrict__ d2) {
    int i = blockIdx.x * blockDim.x + threadIdx.x;
    const float* src; __half* dst; int k = i;
    if (i < WELEM4)               { src = w1; dst = d1; }
    else if (i < 2 * WELEM4)      { src = w3; dst = d3; k = i - WELEM4; }
    else                          { src = w2; dst = d2; k = i - 2 * WELEM4; }
    float4 v = reinterpret_cast<const float4*>(src)[k];
    uint2 p;
    p.x = pack_h2(v.x, v.y);
    p.y = pack_h2(v.z, v.w);
    reinterpret_cast<uint2*>(dst)[k] = p;
}

// ---------------- grouped GEMM (mma.sync m16n8k16 fp16, fp32 accumulate) ----------------
// FUSED=true : 512 threads, 16 warps as 4x4 grid of 32x32 warp tiles.
//              A=g_xh [M,1024], B1=w1h, B3=w3h; C=g_h (fp16 silu(G)*U)
// FUSED=false: 256 threads, 8 warps as 2x4 grid of 64x32 warp tiles (2 CTAs/SM).
//              A=g_h  [M,3584], B1=w2h;         C=g_yh (fp16, coalesced tile stores)
// 3-stage cp.async pipeline, ONE __syncthreads per kt. Per-element K-summation
// order identical across both layouts.  (R12-validated; unchanged)
template<int KD, bool FUSED, int MINB>
__global__ void __launch_bounds__(FUSED ? 512 : 256, MINB)
k_gemm(const __half* __restrict__ B1g, const __half* __restrict__ B3g) {
    constexpr int NTH   = FUSED ? 512 : 256;
    constexpr int MI    = FUSED ? 2 : 4;           // 16-row groups per warp tile
    constexpr int NB    = FUSED ? 2 : 1;
    constexpr int STAGE = (BM + NB * BN) * PADK;   // halves per stage
    constexpr int NK    = KD / BK;
    constexpr int NROWS = FUSED ? FFD : DD;

    extern __shared__ __half smem[];

    int m0 = blockIdx.y * BM;
    if (m0 >= g_poff[EE]) return;
    int e = 0;
#pragma unroll
    for (int i = 1; i < EE; i++) if (m0 >= g_poff[i]) e = i;

    int n0 = blockIdx.x * BN;
    const __half* Ap  = (FUSED ? g_xh : g_h) + (size_t)m0 * KD;
    const __half* B1p = B1g + ((size_t)e * NROWS + n0) * KD;
    const __half* B3p = FUSED ? (B3g + ((size_t)e * FFD + n0) * KD) : nullptr;

    uint32_t sbase = (uint32_t)__cvta_generic_to_shared(smem);
    int tid = threadIdx.x;

    auto load_stage = [&](int kt, int buf) {
        uint32_t sb = sbase + (uint32_t)buf * STAGE * 2;
        int k0 = kt * BK;
        for (int ch = tid; ch < BM * 8; ch += NTH) {       // A: 128 rows x 8 chunks
            int row = ch >> 3, kc = (ch & 7) * 8;
            cp16(sb + (uint32_t)(row * PADK + kc) * 2, Ap + (size_t)row * KD + k0 + kc);
        }
        for (int ch = tid; ch < BN * 8; ch += NTH) {       // B1: 128 rows x 8 chunks
            int row = ch >> 3, kc = (ch & 7) * 8;
            cp16(sb + (uint32_t)((BM + row) * PADK + kc) * 2,
                 B1p + (size_t)row * KD + k0 + kc);
        }
        if (FUSED) {
            for (int ch = tid; ch < BN * 8; ch += NTH) {   // B3
                int row = ch >> 3, kc = (ch & 7) * 8;
                cp16(sb + (uint32_t)((BM + BN + row) * PADK + kc) * 2,
                     B3p + (size_t)row * KD + k0 + kc);
            }
        }
        cp_commit();
    };

    int warp = tid >> 5, lane = tid & 31;
    int wm = warp >> 2, wn = warp & 3;   // FUSED: 4x4 warps (32x32); else 2x4 (64x32)
    int g = lane >> 2, tg = lane & 3;

    float accG[MI][4][4];
    float accU[MI][4][4];
#pragma unroll
    for (int i = 0; i < MI; i++)
#pragma unroll
        for (int j = 0; j < 4; j++)
#pragma unroll
            for (int l = 0; l < 4; l++) {
                accG[i][j][l] = 0.f;
                if (FUSED) accU[i][j][l] = 0.f;
            }

    load_stage(0, 0);
    load_stage(1, 1);

    int buf = 0;
    for (int kt = 0; kt < NK; ++kt) {
        if (kt < NK - 1) { asm volatile("cp.async.wait_group 1;" ::: "memory"); }
        else             { asm volatile("cp.async.wait_group 0;" ::: "memory"); }
        __syncthreads();   // single barrier per kt; also protects buffer (kt+2)%3 reload

        if (kt + 2 < NK) load_stage(kt + 2, (buf + 2) % NSTAGE);

        const __half* s   = smem + (size_t)buf * STAGE;
        const __half* sA  = s;
        const __half* sB1 = s + BM * PADK;
        const __half* sB3 = sB1 + BN * PADK;

#pragma unroll
        for (int ks = 0; ks < BK / 16; ks++) {       // k16 per mma
            int kk = ks * 16;
            uint32_t a[MI][4];
#pragma unroll
            for (int i = 0; i < MI; i++) {
                int r = wm * (MI * 16) + i * 16 + g;
                a[i][0] = *reinterpret_cast<const uint32_t*>(sA + r * PADK + kk + 2 * tg);
                a[i][1] = *reinterpret_cast<const uint32_t*>(sA + (r + 8) * PADK + kk + 2 * tg);
                a[i][2] = *reinterpret_cast<const uint32_t*>(sA + r * PADK + kk + 8 + 2 * tg);
                a[i][3] = *reinterpret_cast<const uint32_t*>(sA + (r + 8) * PADK + kk + 8 + 2 * tg);
            }
#pragma unroll
            for (int j = 0; j < 4; j++) {
                int n = wn * 32 + j * 8 + g;
                uint32_t b1[2];
                b1[0] = *reinterpret_cast<const uint32_t*>(sB1 + n * PADK + kk + 2 * tg);
                b1[1] = *reinterpret_cast<const uint32_t*>(sB1 + n * PADK + kk + 8 + 2 * tg);
#pragma unroll
                for (int i = 0; i < MI; i++) mma16(accG[i][j], a[i], b1);
                if (FUSED) {
                    uint32_t b3[2];
                    b3[0] = *reinterpret_cast<const uint32_t*>(sB3 + n * PADK + kk + 2 * tg);
                    b3[1] = *reinterpret_cast<const uint32_t*>(sB3 + n * PADK + kk + 8 + 2 * tg);
#pragma unroll
                    for (int i = 0; i < MI; i++) mma16(accU[i][j], a[i], b3);
                }
            }
        }
        buf = (buf + 1) % NSTAGE;
    }

    // epilogue (coalesced tile stores)
#pragma unroll
    for (int i = 0; i < MI; i++) {
        int r = m0 + wm * (MI * 16) + i * 16 + g;
#pragma unroll
        for (int j = 0; j < 4; j++) {
            int c = n0 + wn * 32 + j * 8 + 2 * tg;
            if (FUSED) {
                float h0 = silu_mul(accG[i][j][0], accU[i][j][0]);
                float h1 = silu_mul(accG[i][j][1], accU[i][j][1]);
                float h2 = silu_mul(accG[i][j][2], accU[i][j][2]);
                float h3 = silu_mul(accG[i][j][3], accU[i][j][3]);
                *reinterpret_cast<uint32_t*>(g_h + (size_t)r * FFD + c)       = pack_h2(h0, h1);
                *reinterpret_cast<uint32_t*>(g_h + (size_t)(r + 8) * FFD + c) = pack_h2(h2, h3);
            } else {
                *reinterpret_cast<uint32_t*>(g_yh + (size_t)r * DD + c) =
                    pack_h2(accG[i][j][0], accG[i][j][1]);
                *reinterpret_cast<uint32_t*>(g_yh + (size_t)(r + 8) * DD + c) =
                    pack_h2(accG[i][j][2], accG[i][j][3]);
            }
        }
    }
}

// final weighted combine: exactly 2 terms per token -> deterministic
__global__ void k_combine(float* __restrict__ out) {
    int t = blockIdx.x;
    int s0 = g_slot[2 * t], s1 = g_slot[2 * t + 1];
    float w0 = g_rw[2 * t], w1v = g_rw[2 * t + 1];
    int i = threadIdx.x;   // 256 threads x 4 halves (uint2) each
    uint2 pa = reinterpret_cast<const uint2*>(g_yh + (size_t)s0 * DD)[i];
    uint2 pb = reinterpret_cast<const uint2*>(g_yh + (size_t)s1 * DD)[i];
    __half2 a0 = *reinterpret_cast<__half2*>(&pa.x);
    __half2 a1 = *reinterpret_cast<__half2*>(&pa.y);
    __half2 b0 = *reinterpret_cast<__half2*>(&pb.x);
    __half2 b1 = *reinterpret_cast<__half2*>(&pb.y);
    float4 r;
    r.x = w0 * __low2float(a0)  + w1v * __low2float(b0);
    r.y = w0 * __high2float(a0) + w1v * __high2float(b0);
    r.z = w0 * __low2float(a1)  + w1v * __low2float(b1);
    r.w = w0 * __high2float(a1) + w1v * __high2float(b1);
    reinterpret_cast<float4*>(out + (size_t)t * DD)[i] = r;
}

// ---------------- launch ----------------
extern "C" void kernel_launch(void* const* d_in, const int* in_sizes, int n_in,
                              void* d_out, int out_size) {
    const float* x      = (const float*)d_in[0];
    const float* w1     = (const float*)d_in[1];
    const float* w3     = (const float*)d_in[2];
    const float* w2     = (const float*)d_in[3];
    const float* logits = (const float*)d_in[4];
    float* out = (float*)d_out;

    constexpr int SMEM1 = NSTAGE * (BM + 2 * BN) * PADK * 2;  // 165888 B (1 CTA/SM)
    constexpr int SMEM2 = NSTAGE * (BM + 1 * BN) * PADK * 2;  // 110592 B (2 CTAs/SM)
    cudaFuncSetAttribute((const void*)k_gemm<DD,  true,  1>,
                         cudaFuncAttributeMaxDynamicSharedMemorySize, SMEM1);
    cudaFuncSetAttribute((const void*)k_gemm<FFD, false, 2>,
                         cudaFuncAttributeMaxDynamicSharedMemorySize, SMEM2);

    __half* w1h; cudaGetSymbolAddress((void**)&w1h, g_w1h);
    __half* w3h; cudaGetSymbolAddress((void**)&w3h, g_w3h);
    __half* w2h; cudaGetSymbolAddress((void**)&w2h, g_w2h);

    k_route  <<<TT / 256, 256>>>(logits);
    k_scatter<<<EE, 256>>>();
    k_gather <<<MPMAX, 256>>>(x);
    k_halfw  <<<3 * WELEM4 / 256, 256>>>(w1, w3, w2, w1h, w3h, w2h);

    k_gemm<DD,  true,  1><<<dim3(FFD / BN, MTILES), 512, SMEM1>>>(w1h, w3h);
    k_gemm<FFD, false, 2><<<dim3(DD  / BN, MTILES), 256, SMEM2>>>(w2h, nullptr);

    k_combine<<<TT, 256>>>(out);
}

// round 17
// speedup vs baseline: 1.0175x; 1.0002x over previous
#include <cuda_runtime.h>
#include <cuda_fp16.h>
#include <cstdint>
#include <math.h>

// Problem constants
#define TT   8192
#define DD   1024
#define EE   8
#define FFD  3584

// GEMM tiling (fp16 mma.sync m16n8k16)
#define BM   128
#define BN   128
#define BK   64     // halves per stage-K: 64 x 2B = 128B per row
#define PADK 72     // 72-half row stride: 144B, conflict-free frag loads
#define NSTAGE 3

#define MPMAX  (2*TT + EE*BM)   // 17408 max padded slot rows
#define MTILES (MPMAX/BM)       // 136

// ---------------- scratch (device globals; no allocation allowed) ----------------
__device__ __half g_xh [(size_t)MPMAX * DD];    // gathered fp16 x
__device__ __half g_h  [(size_t)MPMAX * FFD];   // silu(G)*U, fp16
__device__ __half g_yh [(size_t)MPMAX * DD];    // per-slot expert output (fp16)
__device__ __half g_w1h[(size_t)EE * FFD * DD]; // fp16 weights
__device__ __half g_w3h[(size_t)EE * FFD * DD];
__device__ __half g_w2h[(size_t)EE * DD * FFD];
__device__ int    g_perm[MPMAX];
__device__ int    g_ridx[TT * 2];
__device__ float  g_rw  [TT * 2];
__device__ int    g_slot[TT * 2];
__device__ int    g_poff[EE + 1];

// ---------------- helpers ----------------
__device__ __forceinline__ void cp16(uint32_t saddr, const void* gptr) {
    asm volatile("cp.async.cg.shared.global [%0], [%1], 16;" :: "r"(saddr), "l"(gptr));
}
__device__ __forceinline__ void cp_commit() {
    asm volatile("cp.async.commit_group;" ::: "memory");
}
__device__ __forceinline__ void mma16(float (&d)[4], const uint32_t (&a)[4], const uint32_t (&b)[2]) {
    asm volatile(
        "mma.sync.aligned.m16n8k16.row.col.f32.f16.f16.f32 "
        "{%0,%1,%2,%3},{%4,%5,%6,%7},{%8,%9},{%0,%1,%2,%3};"
        : "+f"(d[0]), "+f"(d[1]), "+f"(d[2]), "+f"(d[3])
        : "r"(a[0]), "r"(a[1]), "r"(a[2]), "r"(a[3]), "r"(b[0]), "r"(b[1]));
}
__device__ __forceinline__ float silu_mul(float gv, float uv) {
    return (gv / (1.0f + __expf(-gv))) * uv;
}
__device__ __forceinline__ uint32_t pack_h2(float a, float b) {
    __half2 h = __floats2half2_rn(a, b);
    return *reinterpret_cast<uint32_t*>(&h);
}

// ---------------- routing: softmax-top2 == softmax over the top-2 logits ----------------
__global__ void k_route(const float* __restrict__ logits) {
    int t = blockIdx.x * blockDim.x + threadIdx.x;
    if (t >= TT) return;
    float v[EE];
#pragma unroll
    for (int e = 0; e < EE; e++) v[e] = logits[t * EE + e];
    int i0 = 0; float b0 = v[0];
#pragma unroll
    for (int e = 1; e < EE; e++) if (v[e] > b0) { b0 = v[e]; i0 = e; }
    int i1 = -1; float b1 = -INFINITY;
#pragma unroll
    for (int e = 0; e < EE; e++) if (e != i0 && v[e] > b1) { b1 = v[e]; i1 = e; }
    float w0 = 1.0f / (1.0f + __expf(b1 - b0));
    g_ridx[2 * t] = i0;  g_ridx[2 * t + 1] = i1;
    g_rw  [2 * t] = w0;  g_rw  [2 * t + 1] = 1.0f - w0;
}

// stable (token-order) scatter via ballot scan; deterministic.
// Counting + padded-offset computation folded in: each block scans g_ridx once
// (a pass it effectively pays anyway), derives all experts' padded offsets
// locally, and block 0 publishes g_poff for downstream kernels.
__global__ void k_scatter() {
    int e = blockIdx.x, tid = threadIdx.x;
    int warp = tid >> 5, lane = tid & 31;
    __shared__ int scnt[EE];
    __shared__ int spoff[EE + 1];
    __shared__ int wsum[8];
    __shared__ int base;
    if (tid < EE) scnt[tid] = 0;
    if (tid == 0) base = 0;
    __syncthreads();

    // phase 1: count all experts (register histogram -> shared atomics)
    {
        int local[EE];
#pragma unroll
        for (int k = 0; k < EE; k++) local[k] = 0;
        for (int i = tid; i < 2 * TT; i += 256) local[g_ridx[i]]++;
#pragma unroll
        for (int k = 0; k < EE; k++) if (local[k]) atomicAdd(&scnt[k], local[k]);
    }
    __syncthreads();
    if (tid == 0) {
        int acc = 0;
        spoff[0] = 0;
        for (int k = 0; k < EE; k++) {
            acc += ((scnt[k] + BM - 1) / BM) * BM;
            spoff[k + 1] = acc;
        }
        if (e == 0) {               // publish for gather / GEMMs (all blocks agree)
#pragma unroll
            for (int k = 0; k <= EE; k++) g_poff[k] = spoff[k];
        }
    }
    __syncthreads();
    int off = spoff[e];

    // phase 2: stable scatter for this expert
    for (int b = 0; b < TT; b += 256) {
        int t = b + tid;
        int which = -1;
        if (g_ridx[2 * t] == e) which = 0;
        else if (g_ridx[2 * t + 1] == e) which = 1;
        unsigned mask = __ballot_sync(0xffffffffu, which >= 0);
        int lp = __popc(mask & ((1u << lane) - 1));
        if (lane == 0) wsum[warp] = __popc(mask);
        __syncthreads();
        if (which >= 0) {
            int woff = 0;
#pragma unroll
            for (int w = 0; w < 8; w++) if (w < warp) woff += wsum[w];
            int pos = base + woff + lp;
            g_perm[off + pos] = t;
            g_slot[2 * t + which] = off + pos;
        }
        __syncthreads();
        if (tid == 0) {
            int tot = 0;
#pragma unroll
            for (int w = 0; w < 8; w++) tot += wsum[w];
            base += tot;
        }
        __syncthreads();
    }
    int cnt = scnt[e];
    for (int p = off + cnt + tid; p < spoff[e + 1]; p += 256) g_perm[p] = -1;
}

// gather x rows into slot order, RN-converted to fp16
__global__ void k_gather(const float* __restrict__ x) {
    int row = blockIdx.x;
    if (row >= g_poff[EE]) return;
    int t = g_perm[row];
    int i = threadIdx.x;                     // 256 threads x 4 elems = 1024
    float4 v = make_float4(0.f, 0.f, 0.f, 0.f);
    if (t >= 0) v = reinterpret_cast<const float4*>(x + (size_t)t * DD)[i];
    uint2 p;
    p.x = pack_h2(v.x, v.y);
    p.y = pack_h2(v.z, v.w);
    reinterpret_cast<uint2*>(g_xh + (size_t)row * DD)[i] = p;
}

// convert all three weight tensors fp32 -> fp16 (RN) in one launch
#define WELEM4 (EE * FFD * DD / 4)   // float4 groups per tensor
__global__ void k_halfw(const float* __restrict__ w1, const float* __restrict__ w3,
                        const float* __restrict__ w2,
                        __half* __restrict__ d1, __half* __restrict__ d3,
                        __half* __restrict__ d2) {
    int i = blockIdx.x * blockDim.x + threadIdx.x;
    const float* src; __half* dst; int k = i;
    if (i < WELEM4)               { src = w1; dst = d1; }
    else if (i < 2 * WELEM4)      { src = w3; dst = d3; k = i - WELEM4; }
    else                          { src = w2; dst = d2; k = i - 2 * WELEM4; }
    float4 v = reinterpret_cast<const float4*>(src)[k];
    uint2 p;
    p.x = pack_h2(v.x, v.y);
    p.y = pack_h2(v.z, v.w);
    reinterpret_cast<uint2*>(dst)[k] = p;
}

// ---------------- grouped GEMM (mma.sync m16n8k16 fp16, fp32 accumulate) ----------------
// FUSED=true : 512 threads, 16 warps as 4x4 grid of 32x32 warp tiles.
//              A=g_xh [M,1024], B1=w1h, B3=w3h; C=g_h (fp16 silu(G)*U)
// FUSED=false: 256 threads, 8 warps as 2x4 grid of 64x32 warp tiles (2 CTAs/SM).
//              A=g_h  [M,3584], B1=w2h;         C=g_yh (fp16, coalesced tile stores)
// 3-stage cp.async pipeline, ONE __syncthreads per kt. Per-element K-summation
// order identical across both layouts.  (R12-validated; unchanged)
template<int KD, bool FUSED, int MINB>
__global__ void __launch_bounds__(FUSED ? 512 : 256, MINB)
k_gemm(const __half* __restrict__ B1g, const __half* __restrict__ B3g) {
    constexpr int NTH   = FUSED ? 512 : 256;
    constexpr int MI    = FUSED ? 2 : 4;           // 16-row groups per warp tile
    constexpr int NB    = FUSED ? 2 : 1;
    constexpr int STAGE = (BM + NB * BN) * PADK;   // halves per stage
    constexpr int NK    = KD / BK;
    constexpr int NROWS = FUSED ? FFD : DD;

    extern __shared__ __half smem[];

    int m0 = blockIdx.y * BM;
    if (m0 >= g_poff[EE]) return;
    int e = 0;
#pragma unroll
    for (int i = 1; i < EE; i++) if (m0 >= g_poff[i]) e = i;

    int n0 = blockIdx.x * BN;
    const __half* Ap  = (FUSED ? g_xh : g_h) + (size_t)m0 * KD;
    const __half* B1p = B1g + ((size_t)e * NROWS + n0) * KD;
    const __half* B3p = FUSED ? (B3g + ((size_t)e * FFD + n0) * KD) : nullptr;

    uint32_t sbase = (uint32_t)__cvta_generic_to_shared(smem);
    int tid = threadIdx.x;

    auto load_stage = [&](int kt, int buf) {
        uint32_t sb = sbase + (uint32_t)buf * STAGE * 2;
        int k0 = kt * BK;
        for (int ch = tid; ch < BM * 8; ch += NTH) {       // A: 128 rows x 8 chunks
            int row = ch >> 3, kc = (ch & 7) * 8;
            cp16(sb + (uint32_t)(row * PADK + kc) * 2, Ap + (size_t)row * KD + k0 + kc);
        }
        for (int ch = tid; ch < BN * 8; ch += NTH) {       // B1: 128 rows x 8 chunks
            int row = ch >> 3, kc = (ch & 7) * 8;
            cp16(sb + (uint32_t)((BM + row) * PADK + kc) * 2,
                 B1p + (size_t)row * KD + k0 + kc);
        }
        if (FUSED) {
            for (int ch = tid; ch < BN * 8; ch += NTH) {   // B3
                int row = ch >> 3, kc = (ch & 7) * 8;
                cp16(sb + (uint32_t)((BM + BN + row) * PADK + kc) * 2,
                     B3p + (size_t)row * KD + k0 + kc);
            }
        }
        cp_commit();
    };

    int warp = tid >> 5, lane = tid & 31;
    int wm = warp >> 2, wn = warp & 3;   // FUSED: 4x4 warps (32x32); else 2x4 (64x32)
    int g = lane >> 2, tg = lane & 3;

    float accG[MI][4][4];
    float accU[MI][4][4];
#pragma unroll
    for (int i = 0; i < MI; i++)
#pragma unroll
        for (int j = 0; j < 4; j++)
#pragma unroll
            for (int l = 0; l < 4; l++) {
                accG[i][j][l] = 0.f;
                if (FUSED) accU[i][j][l] = 0.f;
            }

    load_stage(0, 0);
    load_stage(1, 1);

    int buf = 0;
    for (int kt = 0; kt < NK; ++kt) {
        if (kt < NK - 1) { asm volatile("cp.async.wait_group 1;" ::: "memory"); }
        else             { asm volatile("cp.async.wait_group 0;" ::: "memory"); }
        __syncthreads();   // single barrier per kt; also protects buffer (kt+2)%3 reload

        if (kt + 2 < NK) load_stage(kt + 2, (buf + 2) % NSTAGE);

        const __half* s   = smem + (size_t)buf * STAGE;
        const __half* sA  = s;
        const __half* sB1 = s + BM * PADK;
        const __half* sB3 = sB1 + BN * PADK;

#pragma unroll
        for (int ks = 0; ks < BK / 16; ks++) {       // k16 per mma
            int kk = ks * 16;
            uint32_t a[MI][4];
#pragma unroll
            for (int i = 0; i < MI; i++) {
                int r = wm * (MI * 16) + i * 16 + g;
                a[i][0] = *reinterpret_cast<const uint32_t*>(sA + r * PADK + kk + 2 * tg);
                a[i][1] = *reinterpret_cast<const uint32_t*>(sA + (r + 8) * PADK + kk + 2 * tg);
                a[i][2] = *reinterpret_cast<const uint32_t*>(sA + r * PADK + kk + 8 + 2 * tg);
                a[i][3] = *reinterpret_cast<const uint32_t*>(sA + (r + 8) * PADK + kk + 8 + 2 * tg);
            }
#pragma unroll
            for (int j = 0; j < 4; j++) {
                int n = wn * 32 + j * 8 + g;
                uint32_t b1[2];
                b1[0] = *reinterpret_cast<const uint32_t*>(sB1 + n * PADK + kk + 2 * tg);
                b1[1] = *reinterpret_cast<const uint32_t*>(sB1 + n * PADK + kk + 8 + 2 * tg);
#pragma unroll
                for (int i = 0; i < MI; i++) mma16(accG[i][j], a[i], b1);
                if (FUSED) {
                    uint32_t b3[2];
                    b3[0] = *reinterpret_cast<const uint32_t*>(sB3 + n * PADK + kk + 2 * tg);
                    b3[1] = *reinterpret_cast<const uint32_t*>(sB3 + n * PADK + kk + 8 + 2 * tg);
#pragma unroll
                    for (int i = 0; i < MI; i++) mma16(accU[i][j], a[i], b3);
                }
            }
        }
        buf = (buf + 1) % NSTAGE;
    }

    // epilogue (coalesced tile stores)
#pragma unroll
    for (int i = 0; i < MI; i++) {
        int r = m0 + wm * (MI * 16) + i * 16 + g;
#pragma unroll
        for (int j = 0; j < 4; j++) {
            int c = n0 + wn * 32 + j * 8 + 2 * tg;
            if (FUSED) {
                float h0 = silu_mul(accG[i][j][0], accU[i][j][0]);
                float h1 = silu_mul(accG[i][j][1], accU[i][j][1]);
                float h2 = silu_mul(accG[i][j][2], accU[i][j][2]);
                float h3 = silu_mul(accG[i][j][3], accU[i][j][3]);
                *reinterpret_cast<uint32_t*>(g_h + (size_t)r * FFD + c)       = pack_h2(h0, h1);
                *reinterpret_cast<uint32_t*>(g_h + (size_t)(r + 8) * FFD + c) = pack_h2(h2, h3);
            } else {
                *reinterpret_cast<uint32_t*>(g_yh + (size_t)r * DD + c) =
                    pack_h2(accG[i][j][0], accG[i][j][1]);
                *reinterpret_cast<uint32_t*>(g_yh + (size_t)(r + 8) * DD + c) =
                    pack_h2(accG[i][j][2], accG[i][j][3]);
            }
        }
    }
}

// final weighted combine: exactly 2 terms per token -> deterministic
__global__ void k_combine(float* __restrict__ out) {
    int t = blockIdx.x;
    int s0 = g_slot[2 * t], s1 = g_slot[2 * t + 1];
    float w0 = g_rw[2 * t], w1v = g_rw[2 * t + 1];
    int i = threadIdx.x;   // 256 threads x 4 halves (uint2) each
    uint2 pa = reinterpret_cast<const uint2*>(g_yh + (size_t)s0 * DD)[i];
    uint2 pb = reinterpret_cast<const uint2*>(g_yh + (size_t)s1 * DD)[i];
    __half2 a0 = *reinterpret_cast<__half2*>(&pa.x);
    __half2 a1 = *reinterpret_cast<__half2*>(&pa.y);
    __half2 b0 = *reinterpret_cast<__half2*>(&pb.x);
    __half2 b1 = *reinterpret_cast<__half2*>(&pb.y);
    float4 r;
    r.x = w0 * __low2float(a0)  + w1v * __low2float(b0);
    r.y = w0 * __high2float(a0) + w1v * __high2float(b0);
    r.z = w0 * __low2float(a1)  + w1v * __low2float(b1);
    r.w = w0 * __high2float(a1) + w1v * __high2float(b1);
    reinterpret_cast<float4*>(out + (size_t)t * DD)[i] = r;
}

// ---------------- launch ----------------
extern "C" void kernel_launch(void* const* d_in, const int* in_sizes, int n_in,
                              void* d_out, int out_size) {
    const float* x      = (const float*)d_in[0];
    const float* w1     = (const float*)d_in[1];
    const float* w3     = (const float*)d_in[2];
    const float* w2     = (const float*)d_in[3];
    const float* logits = (const float*)d_in[4];
    float* out = (float*)d_out;

    constexpr int SMEM1 = NSTAGE * (BM + 2 * BN) * PADK * 2;  // 165888 B (1 CTA/SM)
    constexpr int SMEM2 = NSTAGE * (BM + 1 * BN) * PADK * 2;  // 110592 B (2 CTAs/SM)
    cudaFuncSetAttribute((const void*)k_gemm<DD,  true,  1>,
                         cudaFuncAttributeMaxDynamicSharedMemorySize, SMEM1);
    cudaFuncSetAttribute((const void*)k_gemm<FFD, false, 2>,
                         cudaFuncAttributeMaxDynamicSharedMemorySize, SMEM2);

    __half* w1h; cudaGetSymbolAddress((void**)&w1h, g_w1h);
    __half* w3h; cudaGetSymbolAddress((void**)&w3h, g_w3h);
    __half* w2h; cudaGetSymbolAddress((void**)&w2h, g_w2h);

    k_route  <<<TT / 256, 256>>>(logits);
    k_scatter<<<EE, 256>>>();
    k_gather <<<MPMAX, 256>>>(x);
    k_halfw  <<<3 * WELEM4 / 256, 256>>>(w1, w3, w2, w1h, w3h, w2h);

    k_gemm<DD,  true,  1><<<dim3(FFD / BN, MTILES), 512, SMEM1>>>(w1h, w3h);
    k_gemm<FFD, false, 2><<<dim3(DD  / BN, MTILES), 256, SMEM2>>>(w2h, nullptr);

    k_combine<<<TT, 256>>>(out);
}